// round 5
// baseline (speedup 1.0000x reference)
#include <cuda_runtime.h>
#include <cstdint>

// SphericalVectorPool: B=1, N=2048, A=2048, S=16 scales, out [A, 4*S] f32.
//
// R4: single fused kernel. Mainloop unchanged (MUFU roofline). Each of the
// 16 a-block groups has 32 y-split CTAs; the last-arriving CTA per group
// (threadfence + atomic counter) reduces the group's partials from L2 with
// float4 __ldcg loads and writes the scaled output. Removes the second
// kernel launch + inter-kernel gap + cold scratch re-read.

namespace {
constexpr int A_TOTAL = 2048;
constexpr int N_TOTAL = 2048;
constexpr int S       = 16;
constexpr int NCH     = 4 * S;              // 64 output channels
constexpr int NSPLIT  = 32;                 // N-dimension partitions
constexpr int CHUNK   = N_TOTAL / NSPLIT;   // 64 input points per CTA
constexpr int BLOCK   = 128;
constexpr int NGROUP  = A_TOTAL / BLOCK;    // 16 a-block groups
constexpr float LOG2E = 1.4426950408889634f;
}

// 32 * 64 * 2048 * 4B = 16 MB scratch for partial sums.
__device__ float g_partial[NSPLIT][NCH][A_TOTAL];
// Per-group arrival counters (zero-initialized; reducer resets -> replayable).
__device__ int g_sem[NGROUP];

__device__ __forceinline__ float ex2f(float x) {
    float y;
    asm("ex2.approx.ftz.f32 %0, %1;" : "=f"(y) : "f"(x));
    return y;
}

__device__ __forceinline__ uint64_t pack2(float lo, float hi) {
    uint64_t v;
    asm("mov.b64 %0, {%1, %2};" : "=l"(v) : "f"(lo), "f"(hi));
    return v;
}

__device__ __forceinline__ void unpack2(float& lo, float& hi, uint64_t v) {
    asm("mov.b64 {%0, %1}, %2;" : "=f"(lo), "=f"(hi) : "l"(v));
}

// d = a * b + d  (packed f32x2)
__device__ __forceinline__ void fma2(uint64_t& d, uint64_t a, uint64_t b) {
    asm("fma.rn.f32x2 %0, %1, %2, %0;" : "+l"(d) : "l"(a), "l"(b));
}

__device__ __forceinline__ float4 ldcg4(const float* p) {
    float4 v;
    asm("ld.global.cg.v4.f32 {%0, %1, %2, %3}, [%4];"
        : "=f"(v.x), "=f"(v.y), "=f"(v.z), "=f"(v.w) : "l"(p));
    return v;
}

__global__ __launch_bounds__(BLOCK, 4) void svp_fused(
    const float* __restrict__ f,
    const float* __restrict__ coords,
    const float* __restrict__ out_coords,
    const float* __restrict__ mu,
    const float* __restrict__ r_norms,
    const float* __restrict__ an0,
    const float* __restrict__ an1,
    float* __restrict__ out)
{
    __shared__ float4 tile[CHUNK];
    __shared__ int s_last;

    const int a  = blockIdx.x * BLOCK + threadIdx.x;
    const int n0 = blockIdx.y * CHUNK;

    // Stage this CTA's chunk of input points into smem as (x, y, z, f).
    for (int j = threadIdx.x; j < CHUNK; j += BLOCK) {
        const int n = n0 + j;
        tile[j] = make_float4(coords[3 * n + 0], coords[3 * n + 1],
                              coords[3 * n + 2], f[n]);
    }

    // Per-scale exp2 argument factors: -log2(e) * mu_s, kept in registers.
    float nmu[S];
    #pragma unroll
    for (int s = 0; s < S; ++s) nmu[s] = -LOG2E * mu[s];

    const float Rx = out_coords[3 * a + 0];
    const float Ry = out_coords[3 * a + 1];
    const float Rz = out_coords[3 * a + 2];

    // accA[s] = {sum e*fi, sum e*gx}; accB[s] = {sum e*gy, sum e*gz}
    uint64_t accA[S], accB[S];
    #pragma unroll
    for (int s = 0; s < S; ++s) { accA[s] = 0ull; accB[s] = 0ull; }

    __syncthreads();

    for (int j = 0; j < CHUNK; ++j) {
        const float4 p = tile[j];                 // broadcast LDS.128
        const float dx = p.x - Rx;
        const float dy = p.y - Ry;
        const float dz = p.z - Rz;
        const float r2   = fmaf(dx, dx, fmaf(dy, dy, dz * dz));
        const float rinv = rsqrtf(r2);            // MUFU.RSQ
        const float r    = r2 * rinv;
        const float fi   = p.w;
        const float g    = fi * rinv;

        const uint64_t fgx = pack2(fi, g * dx);   // {fi, gx}
        const uint64_t gyz = pack2(g * dy, g * dz);

        #pragma unroll
        for (int s = 0; s < S; ++s) {
            const float e = ex2f(r * nmu[s]);     // exp(-mu_s * r)
            const uint64_t e2 = pack2(e, e);
            fma2(accA[s], e2, fgx);               // l=0 and l=1,x
            fma2(accB[s], e2, gyz);               // l=1,y and l=1,z
        }
    }

    // Coalesced partial stores: channel-major, a contiguous.
    const int y = blockIdx.y;
    #pragma unroll
    for (int s = 0; s < S; ++s) {
        float v0, v1x, v1y, v1z;
        unpack2(v0, v1x, accA[s]);
        unpack2(v1y, v1z, accB[s]);
        g_partial[y][s][a]             = v0;
        g_partial[y][S + 3 * s + 0][a] = v1x;
        g_partial[y][S + 3 * s + 1][a] = v1y;
        g_partial[y][S + 3 * s + 2][a] = v1z;
    }

    // ---- group arrival: last CTA of this a-block group reduces ----
    __threadfence();
    if (threadIdx.x == 0) {
        const int prev = atomicAdd(&g_sem[blockIdx.x], 1);
        s_last = (prev == NSPLIT - 1);
    }
    __syncthreads();
    if (!s_last) return;
    if (threadIdx.x == 0) g_sem[blockIdx.x] = 0;   // reset for next replay
    __threadfence();

    // Reduce [NSPLIT][NCH][128a] slice. warp w handles channels w, w+4, ...
    // lane holds float4 across a (32 lanes * 4 = 128 a's).
    const int a_base = blockIdx.x * BLOCK;
    const int w    = threadIdx.x >> 5;
    const int lane = threadIdx.x & 31;
    const int ao   = a_base + lane * 4;

    for (int c = w; c < NCH; c += 4) {
        float4 acc = make_float4(0.f, 0.f, 0.f, 0.f);
        #pragma unroll
        for (int yy = 0; yy < NSPLIT; ++yy) {
            const float4 v = ldcg4(&g_partial[yy][c][ao]);
            acc.x += v.x; acc.y += v.y; acc.z += v.z; acc.w += v.w;
        }

        float scale;
        if (c < S) {
            scale = r_norms[c] * an0[0];
        } else {
            const int c2 = c - S;
            const int s  = c2 / 3;
            const int d  = c2 - 3 * s;
            scale = r_norms[s] * an1[d];
        }

        out[(ao + 0) * NCH + c] = acc.x * scale;
        out[(ao + 1) * NCH + c] = acc.y * scale;
        out[(ao + 2) * NCH + c] = acc.z * scale;
        out[(ao + 3) * NCH + c] = acc.w * scale;
    }
}

extern "C" void kernel_launch(void* const* d_in, const int* in_sizes, int n_in,
                              void* d_out, int out_size) {
    const float* f          = (const float*)d_in[0];
    const float* coords     = (const float*)d_in[1];
    const float* out_coords = (const float*)d_in[2];
    const float* mu         = (const float*)d_in[3];
    const float* r_norms    = (const float*)d_in[4];
    const float* an0        = (const float*)d_in[5];
    const float* an1        = (const float*)d_in[6];
    (void)in_sizes; (void)n_in; (void)out_size;

    dim3 grid(NGROUP, NSPLIT);
    svp_fused<<<grid, BLOCK>>>(f, coords, out_coords, mu,
                               r_norms, an0, an1, (float*)d_out);
}

// round 6
// speedup vs baseline: 1.0890x; 1.0890x over previous
#include <cuda_runtime.h>
#include <cstdint>

// SphericalVectorPool: B=1, N=2048, A=2048, S=16 scales, out [A, 4*S] f32.
//
// R5: same fused kernel as R4, but __launch_bounds__(128, 3): R4's (128,4)
// capped regs at 128 and the fused tail pushed the mainloop into local-mem
// spills (regs=126 pinned at cap, L1 traffic, 48us). With a ~168-reg budget
// the whole kernel fits in registers; MUFU pipe saturates at 12 warps/SM so
// the occupancy loss is free.

namespace {
constexpr int A_TOTAL = 2048;
constexpr int N_TOTAL = 2048;
constexpr int S       = 16;
constexpr int NCH     = 4 * S;              // 64 output channels
constexpr int NSPLIT  = 32;                 // N-dimension partitions
constexpr int CHUNK   = N_TOTAL / NSPLIT;   // 64 input points per CTA
constexpr int BLOCK   = 128;
constexpr int NGROUP  = A_TOTAL / BLOCK;    // 16 a-block groups
constexpr float LOG2E = 1.4426950408889634f;
}

// 32 * 64 * 2048 * 4B = 16 MB scratch for partial sums.
__device__ float g_partial[NSPLIT][NCH][A_TOTAL];
// Per-group arrival counters (zero-initialized; reducer resets -> replayable).
__device__ int g_sem[NGROUP];

__device__ __forceinline__ float ex2f(float x) {
    float y;
    asm("ex2.approx.ftz.f32 %0, %1;" : "=f"(y) : "f"(x));
    return y;
}

__device__ __forceinline__ uint64_t pack2(float lo, float hi) {
    uint64_t v;
    asm("mov.b64 %0, {%1, %2};" : "=l"(v) : "f"(lo), "f"(hi));
    return v;
}

__device__ __forceinline__ void unpack2(float& lo, float& hi, uint64_t v) {
    asm("mov.b64 {%0, %1}, %2;" : "=f"(lo), "=f"(hi) : "l"(v));
}

// d = a * b + d  (packed f32x2)
__device__ __forceinline__ void fma2(uint64_t& d, uint64_t a, uint64_t b) {
    asm("fma.rn.f32x2 %0, %1, %2, %0;" : "+l"(d) : "l"(a), "l"(b));
}

__device__ __forceinline__ float4 ldcg4(const float* p) {
    float4 v;
    asm("ld.global.cg.v4.f32 {%0, %1, %2, %3}, [%4];"
        : "=f"(v.x), "=f"(v.y), "=f"(v.z), "=f"(v.w) : "l"(p));
    return v;
}

__global__ __launch_bounds__(BLOCK, 3) void svp_fused(
    const float* __restrict__ f,
    const float* __restrict__ coords,
    const float* __restrict__ out_coords,
    const float* __restrict__ mu,
    const float* __restrict__ r_norms,
    const float* __restrict__ an0,
    const float* __restrict__ an1,
    float* __restrict__ out)
{
    __shared__ float4 tile[CHUNK];
    __shared__ int s_last;

    const int a  = blockIdx.x * BLOCK + threadIdx.x;
    const int n0 = blockIdx.y * CHUNK;

    // Stage this CTA's chunk of input points into smem as (x, y, z, f).
    for (int j = threadIdx.x; j < CHUNK; j += BLOCK) {
        const int n = n0 + j;
        tile[j] = make_float4(coords[3 * n + 0], coords[3 * n + 1],
                              coords[3 * n + 2], f[n]);
    }

    // Per-scale exp2 argument factors: -log2(e) * mu_s, kept in registers.
    float nmu[S];
    #pragma unroll
    for (int s = 0; s < S; ++s) nmu[s] = -LOG2E * mu[s];

    const float Rx = out_coords[3 * a + 0];
    const float Ry = out_coords[3 * a + 1];
    const float Rz = out_coords[3 * a + 2];

    // accA[s] = {sum e*fi, sum e*gx}; accB[s] = {sum e*gy, sum e*gz}
    uint64_t accA[S], accB[S];
    #pragma unroll
    for (int s = 0; s < S; ++s) { accA[s] = 0ull; accB[s] = 0ull; }

    __syncthreads();

    for (int j = 0; j < CHUNK; ++j) {
        const float4 p = tile[j];                 // broadcast LDS.128
        const float dx = p.x - Rx;
        const float dy = p.y - Ry;
        const float dz = p.z - Rz;
        const float r2   = fmaf(dx, dx, fmaf(dy, dy, dz * dz));
        const float rinv = rsqrtf(r2);            // MUFU.RSQ
        const float r    = r2 * rinv;
        const float fi   = p.w;
        const float g    = fi * rinv;

        const uint64_t fgx = pack2(fi, g * dx);   // {fi, gx}
        const uint64_t gyz = pack2(g * dy, g * dz);

        #pragma unroll
        for (int s = 0; s < S; ++s) {
            const float e = ex2f(r * nmu[s]);     // exp(-mu_s * r)
            const uint64_t e2 = pack2(e, e);
            fma2(accA[s], e2, fgx);               // l=0 and l=1,x
            fma2(accB[s], e2, gyz);               // l=1,y and l=1,z
        }
    }

    // Coalesced partial stores: channel-major, a contiguous.
    const int y = blockIdx.y;
    #pragma unroll
    for (int s = 0; s < S; ++s) {
        float v0, v1x, v1y, v1z;
        unpack2(v0, v1x, accA[s]);
        unpack2(v1y, v1z, accB[s]);
        g_partial[y][s][a]             = v0;
        g_partial[y][S + 3 * s + 0][a] = v1x;
        g_partial[y][S + 3 * s + 1][a] = v1y;
        g_partial[y][S + 3 * s + 2][a] = v1z;
    }

    // ---- group arrival: last CTA of this a-block group reduces ----
    __threadfence();
    if (threadIdx.x == 0) {
        const int prev = atomicAdd(&g_sem[blockIdx.x], 1);
        s_last = (prev == NSPLIT - 1);
    }
    __syncthreads();
    if (!s_last) return;
    if (threadIdx.x == 0) g_sem[blockIdx.x] = 0;   // reset for next replay
    __threadfence();

    // Reduce [NSPLIT][NCH][128a] slice. warp w handles channels w, w+4, ...
    // lane holds float4 across a (32 lanes * 4 = 128 a's).
    const int a_base = blockIdx.x * BLOCK;
    const int w    = threadIdx.x >> 5;
    const int lane = threadIdx.x & 31;
    const int ao   = a_base + lane * 4;

    for (int c = w; c < NCH; c += 4) {
        float4 acc = make_float4(0.f, 0.f, 0.f, 0.f);
        #pragma unroll
        for (int yy = 0; yy < NSPLIT; ++yy) {
            const float4 v = ldcg4(&g_partial[yy][c][ao]);
            acc.x += v.x; acc.y += v.y; acc.z += v.z; acc.w += v.w;
        }

        float scale;
        if (c < S) {
            scale = r_norms[c] * an0[0];
        } else {
            const int c2 = c - S;
            const int s  = c2 / 3;
            const int d  = c2 - 3 * s;
            scale = r_norms[s] * an1[d];
        }

        out[(ao + 0) * NCH + c] = acc.x * scale;
        out[(ao + 1) * NCH + c] = acc.y * scale;
        out[(ao + 2) * NCH + c] = acc.z * scale;
        out[(ao + 3) * NCH + c] = acc.w * scale;
    }
}

extern "C" void kernel_launch(void* const* d_in, const int* in_sizes, int n_in,
                              void* d_out, int out_size) {
    const float* f          = (const float*)d_in[0];
    const float* coords     = (const float*)d_in[1];
    const float* out_coords = (const float*)d_in[2];
    const float* mu         = (const float*)d_in[3];
    const float* r_norms    = (const float*)d_in[4];
    const float* an0        = (const float*)d_in[5];
    const float* an1        = (const float*)d_in[6];
    (void)in_sizes; (void)n_in; (void)out_size;

    dim3 grid(NGROUP, NSPLIT);
    svp_fused<<<grid, BLOCK>>>(f, coords, out_coords, mu,
                               r_norms, an0, an1, (float*)d_out);
}

// round 7
// speedup vs baseline: 1.6534x; 1.5182x over previous
#include <cuda_runtime.h>
#include <cstdint>

// SphericalVectorPool: B=1, N=2048, A=2048, S=16 scales, out [A, 4*S] f32.
//
// R6: revert fusion (R4/R5 falsified: 2-wave tail + reducer stragglers).
// Back to the 30.0us two-kernel structure with two changes:
//  - NSPLIT=37 -> grid 592 = 4 CTAs x 148 SMs exactly (fixes the 86%
//    CTA-imbalance ceiling of the 512-CTA grid). Chunk is dynamic (<=56).
//  - per-scale exp2 args computed with packed mul.rn.f32x2 (8 ops vs 16).

namespace {
constexpr int A_TOTAL = 2048;
constexpr int N_TOTAL = 2048;
constexpr int S       = 16;
constexpr int NCH     = 4 * S;              // 64 output channels
constexpr int NSPLIT  = 37;                 // 16 * 37 = 592 = 4 * 148 SMs
constexpr int CHUNK   = (N_TOTAL + NSPLIT - 1) / NSPLIT;  // 56
constexpr int BLOCK   = 128;
constexpr float LOG2E = 1.4426950408889634f;
}

// 37 * 64 * 2048 * 4B = 18.5 MB scratch for partial sums.
__device__ float g_partial[NSPLIT][NCH][A_TOTAL];

__device__ __forceinline__ float ex2f(float x) {
    float y;
    asm("ex2.approx.ftz.f32 %0, %1;" : "=f"(y) : "f"(x));
    return y;
}

__device__ __forceinline__ uint64_t pack2(float lo, float hi) {
    uint64_t v;
    asm("mov.b64 %0, {%1, %2};" : "=l"(v) : "f"(lo), "f"(hi));
    return v;
}

__device__ __forceinline__ void unpack2(float& lo, float& hi, uint64_t v) {
    asm("mov.b64 {%0, %1}, %2;" : "=f"(lo), "=f"(hi) : "l"(v));
}

// d = a * b + d  (packed f32x2)
__device__ __forceinline__ void fma2(uint64_t& d, uint64_t a, uint64_t b) {
    asm("fma.rn.f32x2 %0, %1, %2, %0;" : "+l"(d) : "l"(a), "l"(b));
}

// packed multiply f32x2
__device__ __forceinline__ uint64_t mul2(uint64_t a, uint64_t b) {
    uint64_t d;
    asm("mul.rn.f32x2 %0, %1, %2;" : "=l"(d) : "l"(a), "l"(b));
    return d;
}

__global__ __launch_bounds__(BLOCK, 4) void svp_main(
    const float* __restrict__ f,
    const float* __restrict__ coords,
    const float* __restrict__ out_coords,
    const float* __restrict__ mu)
{
    __shared__ float4 tile[CHUNK];

    const int a    = blockIdx.x * BLOCK + threadIdx.x;
    const int n0   = blockIdx.y * CHUNK;
    const int jmax = min(CHUNK, N_TOTAL - n0);     // last split is shorter

    // Stage this CTA's chunk of input points into smem as (x, y, z, f).
    for (int j = threadIdx.x; j < CHUNK; j += BLOCK) {
        const int n = n0 + j;
        if (n < N_TOTAL)
            tile[j] = make_float4(coords[3 * n + 0], coords[3 * n + 1],
                                  coords[3 * n + 2], f[n]);
    }

    // Packed per-scale exp2 factors: {-log2e*mu[2p], -log2e*mu[2p+1]}.
    uint64_t nmu2[S / 2];
    #pragma unroll
    for (int p = 0; p < S / 2; ++p)
        nmu2[p] = pack2(-LOG2E * mu[2 * p], -LOG2E * mu[2 * p + 1]);

    const float Rx = out_coords[3 * a + 0];
    const float Ry = out_coords[3 * a + 1];
    const float Rz = out_coords[3 * a + 2];

    // accA[s] = {sum e*fi, sum e*gx}; accB[s] = {sum e*gy, sum e*gz}
    uint64_t accA[S], accB[S];
    #pragma unroll
    for (int s = 0; s < S; ++s) { accA[s] = 0ull; accB[s] = 0ull; }

    __syncthreads();

    for (int j = 0; j < jmax; ++j) {
        const float4 p = tile[j];                 // broadcast LDS.128
        const float dx = p.x - Rx;
        const float dy = p.y - Ry;
        const float dz = p.z - Rz;
        const float r2   = fmaf(dx, dx, fmaf(dy, dy, dz * dz));
        const float rinv = rsqrtf(r2);            // MUFU.RSQ
        const float r    = r2 * rinv;
        const float fi   = p.w;
        const float g    = fi * rinv;

        const uint64_t fgx = pack2(fi, g * dx);   // {fi, gx}
        const uint64_t gyz = pack2(g * dy, g * dz);
        const uint64_t rr  = pack2(r, r);

        #pragma unroll
        for (int pidx = 0; pidx < S / 2; ++pidx) {
            const uint64_t arg2 = mul2(rr, nmu2[pidx]);   // {r*nmu0, r*nmu1}
            float a0f, a1f;
            unpack2(a0f, a1f, arg2);
            const float e0 = ex2f(a0f);
            const float e1 = ex2f(a1f);
            const int s0 = 2 * pidx, s1 = 2 * pidx + 1;
            const uint64_t e02 = pack2(e0, e0);
            const uint64_t e12 = pack2(e1, e1);
            fma2(accA[s0], e02, fgx);
            fma2(accB[s0], e02, gyz);
            fma2(accA[s1], e12, fgx);
            fma2(accB[s1], e12, gyz);
        }
    }

    // Coalesced partial stores: channel-major, a contiguous.
    const int y = blockIdx.y;
    #pragma unroll
    for (int s = 0; s < S; ++s) {
        float v0, v1x, v1y, v1z;
        unpack2(v0, v1x, accA[s]);
        unpack2(v1y, v1z, accB[s]);
        g_partial[y][s][a]             = v0;
        g_partial[y][S + 3 * s + 0][a] = v1x;
        g_partial[y][S + 3 * s + 1][a] = v1y;
        g_partial[y][S + 3 * s + 2][a] = v1z;
    }
}

// Thread per (c, a), a fastest -> coalesced loads. 37-way split reduction
// with 8 rotating accumulators for MLP.
__global__ __launch_bounds__(256, 4) void svp_reduce(
    float* __restrict__ out,
    const float* __restrict__ r_norms,
    const float* __restrict__ an0,
    const float* __restrict__ an1)
{
    const int idx = blockIdx.x * 256 + threadIdx.x;   // over NCH * A
    const int c = idx >> 11;          // / 2048
    const int a = idx & 2047;

    const float* __restrict__ p = &g_partial[0][c][a];
    constexpr int YSTRIDE = NCH * A_TOTAL;            // floats between splits

    float acc[8];
    #pragma unroll
    for (int k = 0; k < 8; ++k) acc[k] = 0.f;

    #pragma unroll
    for (int y = 0; y < NSPLIT; ++y)
        acc[y & 7] += p[y * YSTRIDE];

    const float sum = ((acc[0] + acc[1]) + (acc[2] + acc[3]))
                    + ((acc[4] + acc[5]) + (acc[6] + acc[7]));

    float scale;
    if (c < S) {
        scale = r_norms[c] * an0[0];
    } else {
        const int c2 = c - S;
        const int s  = c2 / 3;
        const int d  = c2 - 3 * s;
        scale = r_norms[s] * an1[d];
    }
    out[a * NCH + c] = sum * scale;
}

extern "C" void kernel_launch(void* const* d_in, const int* in_sizes, int n_in,
                              void* d_out, int out_size) {
    const float* f          = (const float*)d_in[0];
    const float* coords     = (const float*)d_in[1];
    const float* out_coords = (const float*)d_in[2];
    const float* mu         = (const float*)d_in[3];
    const float* r_norms    = (const float*)d_in[4];
    const float* an0        = (const float*)d_in[5];
    const float* an1        = (const float*)d_in[6];
    (void)in_sizes; (void)n_in; (void)out_size;

    dim3 grid(A_TOTAL / BLOCK, NSPLIT);                // 16 x 37 = 592 CTAs
    svp_main<<<grid, BLOCK>>>(f, coords, out_coords, mu);

    const int total = NCH * A_TOTAL;                   // 131072 threads
    svp_reduce<<<total / 256, 256>>>((float*)d_out, r_norms, an0, an1);
}